// round 1
// baseline (speedup 1.0000x reference)
#include <cuda_runtime.h>

// out[b,c,l] = y0[b,c,l] * (mean_l x0[b,c,:] + mean_l y0[b,c,:])
// B=64, C=36, L=4096  -> 2304 rows of 4096 fp32.
// One CTA per row. y row cached in smem so each input is read from HBM once.

static constexpr int L = 4096;
static constexpr int THREADS = 512;
static constexpr int VEC_PER_THREAD = (L / 4) / THREADS;  // 2 float4 per thread

__global__ __launch_bounds__(THREADS, 2)
void rowmean_scale_kernel(const float* __restrict__ x,
                          const float* __restrict__ y,
                          float* __restrict__ out) {
    const long long base = (long long)blockIdx.x * L;
    const float4* __restrict__ x4 = reinterpret_cast<const float4*>(x + base);
    const float4* __restrict__ y4 = reinterpret_cast<const float4*>(y + base);
    float4* __restrict__ o4 = reinterpret_cast<float4*>(out + base);

    __shared__ float4 ys[L / 4];          // 16 KB: the y row
    __shared__ float warp_part[THREADS / 32];
    __shared__ float bcast;

    const int tid = threadIdx.x;

    float s = 0.0f;  // sum of x-row + y-row contributions for this thread
    float4 yreg[VEC_PER_THREAD];

    #pragma unroll
    for (int i = 0; i < VEC_PER_THREAD; i++) {
        const int idx = tid + i * THREADS;
        float4 xv = x4[idx];
        float4 yv = y4[idx];
        yreg[i] = yv;
        ys[idx] = yv;
        s += (xv.x + xv.y) + (xv.z + xv.w);
        s += (yv.x + yv.y) + (yv.z + yv.w);
    }

    // warp reduce
    #pragma unroll
    for (int off = 16; off > 0; off >>= 1)
        s += __shfl_xor_sync(0xFFFFFFFFu, s, off);

    const int warp = tid >> 5;
    const int lane = tid & 31;
    if (lane == 0) warp_part[warp] = s;
    __syncthreads();

    if (warp == 0) {
        float v = (lane < (THREADS / 32)) ? warp_part[lane] : 0.0f;
        #pragma unroll
        for (int off = 8; off > 0; off >>= 1)
            v += __shfl_xor_sync(0xFFFFFFFFu, v, off);
        if (lane == 0) bcast = v * (1.0f / (float)L);
    }
    __syncthreads();

    const float scale = bcast;

    // Multiply from registers (the y values we already hold) — smem copy is
    // a fallback for safety of register pressure, but registers are primary.
    #pragma unroll
    for (int i = 0; i < VEC_PER_THREAD; i++) {
        const int idx = tid + i * THREADS;
        float4 yv = yreg[i];
        float4 r;
        r.x = yv.x * scale;
        r.y = yv.y * scale;
        r.z = yv.z * scale;
        r.w = yv.w * scale;
        o4[idx] = r;
    }
}

extern "C" void kernel_launch(void* const* d_in, const int* in_sizes, int n_in,
                              void* d_out, int out_size) {
    const float* x = (const float*)d_in[0];
    const float* y = (const float*)d_in[1];
    float* out = (float*)d_out;
    const int rows = out_size / L;  // 64*36 = 2304
    rowmean_scale_kernel<<<rows, THREADS>>>(x, y, out);
}